// round 17
// baseline (speedup 1.0000x reference)
#include <cuda_runtime.h>
#include <cuda_fp16.h>
#include <cstdint>

// HypercomplexLinear via DFT-4 diagonalization + fp16 mma.sync m16n8k16.
//   a0 = X0@W0'^T/4 (K=192), a2 = X2@W2'^T/4 (K=192),
//   P = (Xr@Wr^T - Xs@Ws^T)/2, Q = (Xr@Ws^T + Xs@Wr^T)/2   (K=384)
//   out_0=a0+a2+P, out_1=a0-a2+Q, out_2=a0+a2-P, out_3=a0-a2-Q  (+bias)
// G = [Out0|Out2|P|Q] fp16 intermediate, combine pass to fp32 out.
// Round-12 GEMM core (proven optimum of the legacy HMMA path); preps merged
// into one launch. BP worker count fixed: 13824 (4608 a0/a2 + 9216 PQ).

#define M_DIM 6272
#define KX    768

__device__ __half g_Xt[M_DIM * KX];   // [X0|X2|Xr|Xs], canonical k order
// a0 tiles [0,147456): 6 x (3 chunks x 128n x 64k); a2 [147456,294912);
// PQ [294912,...): 12 x (6 chunks x 128n x 64k)  (0..5=P, 6..11=Q)
__device__ __half g_Bp[884736];
__device__ __half g_G[M_DIM * 3072];  // fp16 intermediate

// ---------------------------------------------------------------------------
// Merged prep: blocks [0,2352) transform X (2 cols/thread, 602k threads);
// blocks [2352,2406) pack weights (13824 workers).
// ---------------------------------------------------------------------------
#define XT_BLOCKS 2352
#define BP_BLOCKS 54
#define BP_WORKERS 13824

__global__ void prep_kernel(const float* __restrict__ x,
                            const float* __restrict__ w) {
    if (blockIdx.x < XT_BLOCKS) {
        int idx = blockIdx.x * 256 + threadIdx.x;      // 6272*96
        int b   = idx / 96;
        int c2  = (idx - b * 96) * 2;
        const float* xb = x + (size_t)b * KX;
        float2 v0 = *reinterpret_cast<const float2*>(xb + c2);
        float2 v1 = *reinterpret_cast<const float2*>(xb + 192 + c2);
        float2 v2 = *reinterpret_cast<const float2*>(xb + 384 + c2);
        float2 v3 = *reinterpret_cast<const float2*>(xb + 576 + c2);
        __half* yb = g_Xt + (size_t)b * KX + c2;
        float ex = v0.x + v2.x, ey = v0.y + v2.y;
        float ox = v1.x + v3.x, oy = v1.y + v3.y;
        float rx = v0.x - v2.x, ry = v0.y - v2.y;
        float sx = v1.x - v3.x, sy = v1.y - v3.y;
        __half2 h;
        h = __floats2half2_rn(ex + ox, ey + oy);
        *reinterpret_cast<__half2*>(yb)       = h;
        h = __floats2half2_rn(ex - ox, ey - oy);
        *reinterpret_cast<__half2*>(yb + 192) = h;
        h = __floats2half2_rn(rx, ry);
        *reinterpret_cast<__half2*>(yb + 384) = h;
        h = __floats2half2_rn(sx, sy);
        *reinterpret_cast<__half2*>(yb + 576) = h;
        return;
    }

    int idx = (blockIdx.x - XT_BLOCKS) * 256 + threadIdx.x;   // 0..13823
    if (idx >= BP_WORKERS) return;
    float val[64];
    __half* dst;
    if (idx < 4608) {                       // a0 / a2
        int cmp  = idx / 2304;
        int rr   = idx - cmp * 2304;
        int tile = rr / 384;
        int rem  = rr - tile * 384;
        int cc   = rem >> 7;                // chunk 0..2
        int n    = rem & 127;
        int o    = tile * 128 + n;
        const float* b0 = w + o * 192 + cc * 64;
        float sg = cmp ? -1.0f : 1.0f;
#pragma unroll 8
        for (int kk = 0; kk < 64; kk++) {
            float w0 = b0[kk], w1 = b0[147456 + kk];
            float w2 = b0[294912 + kk], w3 = b0[442368 + kk];
            val[kk] = 0.25f * (w0 + sg * w1 + w2 + sg * w3);
        }
        dst = g_Bp + cmp * 147456 + tile * 24576 + cc * 8192 + n * 64;
    } else {                                // PQ
        int i2   = idx - 4608;              // 0..9215
        int t12  = i2 / 768;                // 0..11
        int rem  = i2 - t12 * 768;
        int cc   = rem >> 7;                // chunk 0..5
        int n    = rem & 127;
        int isQ  = t12 >= 6;
        int o    = (t12 % 6) * 128 + n;
        int ccx  = (cc < 3 ? cc : cc - 3) * 64;
        const float* b0 = w + o * 192 + ccx;
#pragma unroll 8
        for (int kk = 0; kk < 64; kk++) {
            float d02 = b0[kk] - b0[294912 + kk];
            float d13 = b0[147456 + kk] - b0[442368 + kk];
            float pv, qv;
            if (cc < 3) { pv = 0.5f * d02;  qv = 0.5f * d13; }
            else        { pv = -0.5f * d13; qv = 0.5f * d02; }
            val[kk] = isQ ? qv : pv;
        }
        dst = g_Bp + 294912 + t12 * 49152 + cc * 8192 + n * 64;
    }
    __half h[64];
#pragma unroll
    for (int kk = 0; kk < 64; kk++) h[kk] = __float2half_rn(val[kk]);
#pragma unroll
    for (int q = 0; q < 8; q++)
        reinterpret_cast<uint4*>(dst)[q] = reinterpret_cast<const uint4*>(h)[q];
}

// ---------------------------------------------------------------------------
// fp16 GEMM with ldmatrix. CTA 128x128, K-chunk 64, 3-stage cp.async.
// 2 CTAs/SM (96KB smem each). Heavy (K=384) tiles scheduled first.
// ---------------------------------------------------------------------------
#define STAGES 3
#define STG_B 32768
#define SMEM_BYTES (STAGES * STG_B)

__device__ __forceinline__ void mma_f16(float* c, uint32_t a0, uint32_t a1,
                                        uint32_t a2, uint32_t a3,
                                        uint32_t b0, uint32_t b1) {
    asm volatile(
        "mma.sync.aligned.m16n8k16.row.col.f32.f16.f16.f32 "
        "{%0,%1,%2,%3}, {%4,%5,%6,%7}, {%8,%9}, {%0,%1,%2,%3};"
        : "+f"(c[0]), "+f"(c[1]), "+f"(c[2]), "+f"(c[3])
        : "r"(a0), "r"(a1), "r"(a2), "r"(a3), "r"(b0), "r"(b1));
}
#define LDSM_X4(r0, r1, r2, r3, a) \
    asm volatile("ldmatrix.sync.aligned.m8n8.x4.shared.b16 {%0,%1,%2,%3}, [%4];" \
                 : "=r"(r0), "=r"(r1), "=r"(r2), "=r"(r3) : "r"(a))

__global__ __launch_bounds__(256, 2)
void gemm_f16_kernel() {
    extern __shared__ char smem[];
    const int nt  = (blockIdx.x + 12) % 24;   // heavy PQ tiles (12..23) first
    const int bm  = blockIdx.y * 128;
    const int bn  = nt * 128;

    int aoff, KT;
    const __half* Bg;
    if (nt < 6)       { aoff = 0;   KT = 3; Bg = g_Bp + nt * 24576; }
    else if (nt < 12) { aoff = 192; KT = 3; Bg = g_Bp + 147456 + (nt - 6) * 24576; }
    else              { aoff = 384; KT = 6; Bg = g_Bp + 294912 + (nt - 12) * 49152; }

    const int tid  = threadIdx.x;
    const int warp = tid >> 5;
    const int lane = tid & 31;
    const int g    = lane >> 2;
    const int tig  = lane & 3;
    const int wm   = (warp & 1) * 64;
    const int wn   = (warp >> 1) * 32;

    float acc[4][4][4];
#pragma unroll
    for (int mi = 0; mi < 4; mi++)
#pragma unroll
        for (int ni = 0; ni < 4; ni++)
#pragma unroll
            for (int r = 0; r < 4; r++) acc[mi][ni][r] = 0.0f;

    // cp.async loader: 2 threads per row, 4 x 16B chunks each
    const int lrow = tid >> 1;
    const int cseg = (tid & 1) * 4;
    const int ssw  = lrow & 7;
    const char* gA = reinterpret_cast<const char*>(
        g_Xt + (size_t)(bm + lrow) * KX + aoff);
    const char* gB = reinterpret_cast<const char*>(Bg + lrow * 64);
    uint32_t sbase;
    asm("{ .reg .u64 t; cvta.to.shared.u64 t, %1; cvt.u32.u64 %0, t; }"
        : "=r"(sbase) : "l"(smem));

    auto load_stage = [&](int kt, int s) {
        uint32_t ab = sbase + (uint32_t)(s * STG_B);
        uint32_t bb = ab + 16384u;
#pragma unroll
        for (int f = 0; f < 4; f++) {
            int c = cseg + f;
            uint32_t wd = (uint32_t)(lrow * 128 + ((c ^ ssw) << 4));
            asm volatile("cp.async.cg.shared.global [%0], [%1], 16;"
                         :: "r"(ab + wd), "l"(gA + kt * 128 + c * 16));
            asm volatile("cp.async.cg.shared.global [%0], [%1], 16;"
                         :: "r"(bb + wd), "l"(gB + kt * 16384 + c * 16));
        }
    };

    // ldmatrix per-lane row mapping
    const int rowA = (lane & 7) + ((lane >> 3) & 1) * 8;
    const int chA  = lane >> 4;
    const int rowB = (lane & 7) + ((lane >> 4) & 1) * 8;
    const int chB  = (lane >> 3) & 1;
    int rA[4], rB[2];
#pragma unroll
    for (int mi = 0; mi < 4; mi++) rA[mi] = wm + mi * 16 + rowA;
#pragma unroll
    for (int n2 = 0; n2 < 2; n2++) rB[n2] = wn + n2 * 16 + rowB;

    auto compute = [&](int s) {
        uint32_t As = sbase + (uint32_t)(s * STG_B);
        uint32_t Bs = As + 16384u;
#pragma unroll
        for (int kg = 0; kg < 4; kg++) {
            uint32_t af[4][4], bf[2][4];
#pragma unroll
            for (int mi = 0; mi < 4; mi++) {
                uint32_t ad = As + (uint32_t)(rA[mi] * 128
                            + (((2 * kg + chA) ^ (rA[mi] & 7)) << 4));
                LDSM_X4(af[mi][0], af[mi][1], af[mi][2], af[mi][3], ad);
            }
#pragma unroll
            for (int n2 = 0; n2 < 2; n2++) {
                uint32_t bd = Bs + (uint32_t)(rB[n2] * 128
                            + (((2 * kg + chB) ^ (rB[n2] & 7)) << 4));
                LDSM_X4(bf[n2][0], bf[n2][1], bf[n2][2], bf[n2][3], bd);
            }
#pragma unroll
            for (int ni = 0; ni < 4; ni++) {
                uint32_t b0 = bf[ni >> 1][(ni & 1) * 2];
                uint32_t b1 = bf[ni >> 1][(ni & 1) * 2 + 1];
#pragma unroll
                for (int mi = 0; mi < 4; mi++)
                    mma_f16(acc[mi][ni], af[mi][0], af[mi][1], af[mi][2], af[mi][3],
                            b0, b1);
            }
        }
    };

    int fetch = 0;
#pragma unroll
    for (int s = 0; s < STAGES - 1; s++) {
        if (fetch < KT) load_stage(fetch, s);
        asm volatile("cp.async.commit_group;");
        fetch++;
    }
    asm volatile("cp.async.wait_group %0;" :: "n"(STAGES - 2));
    __syncthreads();

    for (int kt = 0; kt < KT; kt++) {
        if (fetch < KT) load_stage(fetch, fetch % STAGES);
        asm volatile("cp.async.commit_group;");
        fetch++;
        compute(kt % STAGES);
        asm volatile("cp.async.wait_group %0;" :: "n"(STAGES - 2));
        __syncthreads();
    }

    // Epilogue: acc -> fp16 smem tile (row stride 136) -> coalesced stores
    __half* sg = reinterpret_cast<__half*>(smem);
#pragma unroll
    for (int mi = 0; mi < 4; mi++) {
        int row0 = wm + mi * 16 + g;
#pragma unroll
        for (int ni = 0; ni < 4; ni++) {
            int col = wn + ni * 8 + 2 * tig;
            *reinterpret_cast<__half2*>(sg + row0 * 136 + col) =
                __floats2half2_rn(acc[mi][ni][0], acc[mi][ni][1]);
            *reinterpret_cast<__half2*>(sg + (row0 + 8) * 136 + col) =
                __floats2half2_rn(acc[mi][ni][2], acc[mi][ni][3]);
        }
    }
    __syncthreads();
#pragma unroll
    for (int i = 0; i < 8; i++) {
        int linear = tid + 256 * i;
        int row = linear >> 4;
        int q   = linear & 15;
        uint4 v = *reinterpret_cast<const uint4*>(sg + row * 136 + q * 8);
        *reinterpret_cast<uint4*>(g_G + (size_t)(bm + row) * 3072 + bn + q * 8) = v;
    }
}

// ---------------------------------------------------------------------------
// Combine: fp16 G -> fp32 out with bias. One thread per (b, 2 o) — 2.4M thr.
// ---------------------------------------------------------------------------
__global__ void combine_kernel(const float* __restrict__ bias,
                               float* __restrict__ out) {
    int idx = blockIdx.x * blockDim.x + threadIdx.x;   // 6272*384
    int b  = idx / 384;
    int o2 = (idx - b * 384) * 2;
    const __half* Gb = g_G + (size_t)b * 3072;
    __half2 a0 = *reinterpret_cast<const __half2*>(Gb + o2);
    __half2 a2 = *reinterpret_cast<const __half2*>(Gb + 768 + o2);
    __half2 p  = *reinterpret_cast<const __half2*>(Gb + 1536 + o2);
    __half2 q  = *reinterpret_cast<const __half2*>(Gb + 2304 + o2);

    float2 fa0 = __half22float2(a0);
    float2 fa2 = __half22float2(a2);
    float2 fp  = __half22float2(p);
    float2 fq  = __half22float2(q);
    float sx = fa0.x + fa2.x, sy = fa0.y + fa2.y;
    float dx = fa0.x - fa2.x, dy = fa0.y - fa2.y;

    const float2 bv0 = *reinterpret_cast<const float2*>(bias + o2);
    const float2 bv1 = *reinterpret_cast<const float2*>(bias + 768 + o2);
    const float2 bv2 = *reinterpret_cast<const float2*>(bias + 1536 + o2);
    const float2 bv3 = *reinterpret_cast<const float2*>(bias + 2304 + o2);

    float* ob = out + (size_t)b * 3072 + o2;
    *reinterpret_cast<float2*>(ob)        = make_float2(sx + fp.x + bv0.x, sy + fp.y + bv0.y);
    *reinterpret_cast<float2*>(ob + 768)  = make_float2(dx + fq.x + bv1.x, dy + fq.y + bv1.y);
    *reinterpret_cast<float2*>(ob + 1536) = make_float2(sx - fp.x + bv2.x, sy - fp.y + bv2.y);
    *reinterpret_cast<float2*>(ob + 2304) = make_float2(dx - fq.x + bv3.x, dy - fq.y + bv3.y);
}

// ---------------------------------------------------------------------------
extern "C" void kernel_launch(void* const* d_in, const int* in_sizes, int n_in,
                              void* d_out, int out_size) {
    const float* x    = (const float*)d_in[0];
    const float* w    = (const float*)d_in[1];
    const float* bias = (const float*)d_in[2];
    float* out = (float*)d_out;

    cudaFuncSetAttribute(gemm_f16_kernel,
                         cudaFuncAttributeMaxDynamicSharedMemorySize, SMEM_BYTES);

    prep_kernel<<<XT_BLOCKS + BP_BLOCKS, 256>>>(x, w);  // 2406 blocks

    dim3 grid(24, 49);
    gemm_f16_kernel<<<grid, 256, SMEM_BYTES>>>();

    combine_kernel<<<(M_DIM * 384) / 256, 256>>>(bias, out);  // 9408 blocks
}